// round 8
// baseline (speedup 1.0000x reference)
#include <cuda_runtime.h>
#include <cuda_bf16.h>
#include <cstdint>

#define BATCH 64
#define SEQ   512
#define DIN   256
#define UNITS 512
#define M_TOT (BATCH * SEQ)   // 32768

// ---------------- scratch (module-static, no allocation APIs) ----------------
__device__ float         g_xT[(size_t)M_TOT * UNITS];   // 64 MB, row-major [M][512]
__device__ __nv_bfloat16 g_Ah[(size_t)M_TOT * DIN];     // 16 MB, [M][K]
__device__ __nv_bfloat16 g_Al[(size_t)M_TOT * DIN];
__device__ __nv_bfloat16 g_Bh[(size_t)UNITS * DIN];     // 256 KB, [N][K] (T transposed)
__device__ __nv_bfloat16 g_Bl[(size_t)UNITS * DIN];

// ---------------- PTX helpers ----------------
static __device__ __forceinline__ uint32_t smem_u32(const void* p) {
    uint32_t a;
    asm("{ .reg .u64 t; cvta.to.shared.u64 t, %1; cvt.u32.u64 %0, t; }" : "=r"(a) : "l"(p));
    return a;
}
static __device__ __forceinline__ void cp16(uint32_t dst, const void* src) {
    asm volatile("cp.async.cg.shared.global [%0], [%1], 16;" :: "r"(dst), "l"(src));
}
static __device__ __forceinline__ void cp_commit() { asm volatile("cp.async.commit_group;"); }
template <int N> static __device__ __forceinline__ void cp_wait() {
    asm volatile("cp.async.wait_group %0;" :: "n"(N));
}

static __device__ __forceinline__ void ldmx4(uint32_t& r0, uint32_t& r1,
                                             uint32_t& r2, uint32_t& r3, uint32_t addr) {
    asm volatile("ldmatrix.sync.aligned.m8n8.x4.shared.b16 {%0,%1,%2,%3}, [%4];"
                 : "=r"(r0), "=r"(r1), "=r"(r2), "=r"(r3) : "r"(addr));
}
static __device__ __forceinline__ void mma16816(float* c, const uint32_t* a,
                                                uint32_t b0, uint32_t b1) {
    asm volatile(
        "mma.sync.aligned.m16n8k16.row.col.f32.bf16.bf16.f32 "
        "{%0,%1,%2,%3}, {%4,%5,%6,%7}, {%8,%9}, {%0,%1,%2,%3};"
        : "+f"(c[0]), "+f"(c[1]), "+f"(c[2]), "+f"(c[3])
        : "r"(a[0]), "r"(a[1]), "r"(a[2]), "r"(a[3]), "r"(b0), "r"(b1));
}

// ---------------- conversion kernels ----------------
__global__ __launch_bounds__(256)
void convert_x_kernel(const float* __restrict__ x) {
    size_t i4 = (size_t)blockIdx.x * 256 + threadIdx.x;   // 4-element groups
    float4 v = ((const float4*)x)[i4];
    float vv[4] = {v.x, v.y, v.z, v.w};
    unsigned short hs[4], ls[4];
#pragma unroll
    for (int j = 0; j < 4; j++) {
        __nv_bfloat16 h = __float2bfloat16_rn(vv[j]);
        __nv_bfloat16 l = __float2bfloat16_rn(vv[j] - __bfloat162float(h));
        hs[j] = *reinterpret_cast<unsigned short*>(&h);
        ls[j] = *reinterpret_cast<unsigned short*>(&l);
    }
    ((uint2*)g_Ah)[i4] = make_uint2((uint32_t)hs[0] | ((uint32_t)hs[1] << 16),
                                    (uint32_t)hs[2] | ((uint32_t)hs[3] << 16));
    ((uint2*)g_Al)[i4] = make_uint2((uint32_t)ls[0] | ((uint32_t)ls[1] << 16),
                                    (uint32_t)ls[2] | ((uint32_t)ls[3] << 16));
}

__global__ __launch_bounds__(256)
void convert_T_kernel(const float* __restrict__ T) {
    int idx = blockIdx.x * 256 + threadIdx.x;   // idx = k*512 + n
    int k = idx >> 9;
    int n = idx & 511;
    float v = T[idx];
    __nv_bfloat16 h = __float2bfloat16_rn(v);
    __nv_bfloat16 l = __float2bfloat16_rn(v - __bfloat162float(h));
    g_Bh[(size_t)n * DIN + k] = h;
    g_Bl[(size_t)n * DIN + k] = l;
}

// ---------------- mma.sync GEMM: g_xT = x @ T via split bf16 (3 terms) ----------------
// Tile 128x128, BK=64, 2-stage cp.async, 16 warps (4m x 4n), warp tile 32x32.
// Fragment double-buffering across the 12 (pass, ks) steps hides LDSM latency.
// SMEM stage: Ah@0, Al@16K, Bh@32K, Bl@48K, each [128 rows][64 bf16] SW128-swizzled.
#define GS_STAGE 65536

static __device__ __forceinline__ void gemm_load_chunk(uint32_t sb, int tid,
                                                       int m0, int n0, int kc) {
    const int k0b = kc * 128;   // 64 bf16 = 128 bytes along K
    const char* bases[4] = {
        (const char*)(g_Ah + (size_t)m0 * DIN), (const char*)(g_Al + (size_t)m0 * DIN),
        (const char*)(g_Bh + (size_t)n0 * DIN), (const char*)(g_Bl + (size_t)n0 * DIN)
    };
#pragma unroll
    for (int t = 0; t < 4; t++) {
        const char* g = bases[t];
#pragma unroll
        for (int i = 0; i < 2; i++) {
            int u = tid + i * 512;           // 0..1023
            int row = u >> 3, ku = u & 7;
            uint32_t off = (uint32_t)(row * 128 + ku * 16);
            uint32_t sw = off ^ ((off >> 3) & 0x70);
            cp16(sb + t * 16384 + sw, g + (size_t)row * 512 + k0b + ku * 16);
        }
    }
    cp_commit();
}

// swizzled smem address for (row, byte-col) inside a [128][128B] tile
static __device__ __forceinline__ uint32_t sw_addr(uint32_t base, int row, int colb) {
    return base + (uint32_t)(row * 128) + (uint32_t)(colb ^ ((row & 7) << 4));
}

__global__ __launch_bounds__(512, 1)
void gemm_kernel() {
    extern __shared__ __align__(1024) char sm[];
    const uint32_t sbase = smem_u32(sm);
    const int tid = threadIdx.x;
    const int wid = tid >> 5, lid = tid & 31;
    const int warp_m = wid & 3;        // 4 m-groups of 32 rows
    const int warp_n = wid >> 2;       // 4 n-groups of 32 cols
    const int m0 = blockIdx.y * 128;
    const int n0 = blockIdx.x * 128;

    const int lrow = lid & 15;         // row within 16-row ldmatrix group
    const int lqc  = (lid >> 4) * 16;  // +16B for k8-15 quads
    const int arow0 = warp_m * 32 + lrow;
    const int brow0 = warp_n * 32 + lrow;

    float acc[2][4][4];
#pragma unroll
    for (int i = 0; i < 2; i++)
#pragma unroll
        for (int j = 0; j < 4; j++)
#pragma unroll
            for (int q = 0; q < 4; q++) acc[i][j][q] = 0.0f;

    uint32_t af[2][2][4];   // [buf][mt][frag]
    uint32_t bf[2][4][2];   // [buf][nt][frag]

    gemm_load_chunk(sbase, tid, m0, n0, 0);
    gemm_load_chunk(sbase + GS_STAGE, tid, m0, n0, 1);

#pragma unroll
    for (int kc = 0; kc < 4; kc++) {
        if (kc < 3) cp_wait<1>(); else cp_wait<0>();
        __syncthreads();
        const uint32_t sb = sbase + (kc & 1) * GS_STAGE;
        // pass 0: Ah*Bh, pass 1: Ah*Bl, pass 2: Al*Bh
        const uint32_t aS[3] = {sb, sb, sb + 16384};
        const uint32_t bS[3] = {sb + 32768, sb + 49152, sb + 32768};

#define LOAD_FRAGS(buf, step) do {                                              \
            const uint32_t _a = aS[(step) >> 2], _b = bS[(step) >> 2];          \
            const int _kb = ((step) & 3) * 32 + lqc;                            \
            ldmx4(af[buf][0][0], af[buf][0][1], af[buf][0][2], af[buf][0][3],   \
                  sw_addr(_a, arow0, _kb));                                     \
            ldmx4(af[buf][1][0], af[buf][1][1], af[buf][1][2], af[buf][1][3],   \
                  sw_addr(_a, arow0 + 16, _kb));                                \
            _Pragma("unroll")                                                   \
            for (int ng = 0; ng < 2; ng++) {                                    \
                uint32_t r0, r1, r2, r3;                                        \
                ldmx4(r0, r1, r2, r3, sw_addr(_b, brow0 + ng * 16, _kb));       \
                bf[buf][2 * ng][0] = r0; bf[buf][2 * ng + 1][0] = r1;           \
                bf[buf][2 * ng][1] = r2; bf[buf][2 * ng + 1][1] = r3;           \
            }                                                                   \
        } while (0)

        LOAD_FRAGS(0, 0);
#pragma unroll
        for (int s = 0; s < 12; s++) {
            if (s < 11) LOAD_FRAGS((s + 1) & 1, s + 1);
#pragma unroll
            for (int mt = 0; mt < 2; mt++)
#pragma unroll
                for (int nt = 0; nt < 4; nt++)
                    mma16816(acc[mt][nt], af[s & 1][mt], bf[s & 1][nt][0], bf[s & 1][nt][1]);
        }
#undef LOAD_FRAGS
        __syncthreads();
        if (kc < 2) gemm_load_chunk(sb, tid, m0, n0, kc + 2);
    }

    // Epilogue: write c-fragments directly (float2 per quad-half).
    const int gID = lid >> 2, tg = lid & 3;
#pragma unroll
    for (int mt = 0; mt < 2; mt++) {
#pragma unroll
        for (int nt = 0; nt < 4; nt++) {
            int m_lo = m0 + warp_m * 32 + mt * 16 + gID;
            int n    = n0 + warp_n * 32 + nt * 8 + tg * 2;
            *(float2*)(g_xT + (size_t)m_lo * UNITS + n) =
                make_float2(acc[mt][nt][0], acc[mt][nt][1]);
            *(float2*)(g_xT + (size_t)(m_lo + 8) * UNITS + n) =
                make_float2(acc[mt][nt][2], acc[mt][nt][3]);
        }
    }
}

// ---------------- scan kernel: smem-staged block-diagonal recurrence ----------------
// B = expm(skew, even-position couplings) is EXACTLY 2x2 block diagonal. One
// thread per (batch, pair); 32-step chunks staged via 4-deep cp.async ring.
// 256 CTAs x 64 threads spread across all SMs.
__global__ __launch_bounds__(64, 1)
void scan_kernel(const float* __restrict__ Bfull, const float* __restrict__ bias,
                 const float* __restrict__ h0, float* __restrict__ out) {
    extern __shared__ __align__(1024) char sm[];   // 4 x 16KB
    const uint32_t sbase = smem_u32(sm);
    const int tid = threadIdx.x;
    const int b = blockIdx.y;
    const int u0 = blockIdx.x * 128;
    const int u = u0 + 2 * tid;

    const float B00 = Bfull[(size_t)u * UNITS + u];
    const float B01 = Bfull[(size_t)u * UNITS + u + 1];
    const float B10 = Bfull[(size_t)(u + 1) * UNITS + u];
    const float B11 = Bfull[(size_t)(u + 1) * UNITS + u + 1];
    const float2 bi = *(const float2*)(bias + u);
    float2 h = *(const float2*)(h0 + u);

    const float* xbase = g_xT + (size_t)b * SEQ * UNITS + u0;

    // load 32 rows x 128 floats (16KB) into ring stage tc&3
#define SCAN_LOAD(tc) do {                                                       \
        uint32_t dst = sbase + ((tc) & 3) * 16384;                               \
        const float* src = xbase + (size_t)(tc) * 32 * UNITS;                    \
        _Pragma("unroll")                                                        \
        for (int i = 0; i < 16; i++) {                                           \
            int uq = tid + i * 64;                                               \
            int row = uq >> 5, cu = uq & 31;                                     \
            cp16(dst + row * 512 + cu * 16, src + (size_t)row * UNITS + cu * 4); \
        }                                                                        \
        cp_commit();                                                             \
    } while (0)

    SCAN_LOAD(0);
    SCAN_LOAD(1);
    SCAN_LOAD(2);
    SCAN_LOAD(3);

    float2* op = (float2*)(out + (size_t)b * UNITS + u0) + tid;   // +t*16384 float2/step

    for (int tc = 0; tc < 16; tc++) {
        if (tc < 12) cp_wait<3>(); else cp_wait<0>();
        __syncthreads();
        const float2* xs = (const float2*)(sm + (tc & 3) * 16384) + tid;
#pragma unroll
        for (int lt = 0; lt < 32; lt++) {
            float2 xv = xs[lt * 64];
            float z0 = fmaf(h.y, B10, fmaf(h.x, B00, xv.x));
            float z1 = fmaf(h.y, B11, fmaf(h.x, B01, xv.y));
            float m0 = fmaxf(fabsf(z0) + bi.x, 0.0f);
            float m1 = fmaxf(fabsf(z1) + bi.y, 0.0f);
            h.x = (z0 > 0.0f) ? m0 : ((z0 < 0.0f) ? -m0 : 0.0f);
            h.y = (z1 > 0.0f) ? m1 : ((z1 < 0.0f) ? -m1 : 0.0f);
            op[(size_t)(tc * 32 + lt) * (BATCH * UNITS / 2)] = h;
        }
        __syncthreads();
        if (tc + 4 < 16) SCAN_LOAD(tc + 4);
    }
#undef SCAN_LOAD
}

// ---------------- launch ----------------
extern "C" void kernel_launch(void* const* d_in, const int* in_sizes, int n_in,
                              void* d_out, int out_size) {
    const float* x    = (const float*)d_in[0];
    const float* T    = (const float*)d_in[1];
    const float* B    = (const float*)d_in[2];
    const float* bias = (const float*)d_in[3];
    const float* h0   = (const float*)d_in[4];
    float* out        = (float*)d_out;
    (void)in_sizes; (void)n_in; (void)out_size;

    cudaFuncSetAttribute(gemm_kernel, cudaFuncAttributeMaxDynamicSharedMemorySize,
                         2 * GS_STAGE);
    cudaFuncSetAttribute(scan_kernel, cudaFuncAttributeMaxDynamicSharedMemorySize, 65536);

    convert_x_kernel<<<(M_TOT * DIN / 4) / 256, 256>>>(x);       // 8192 CTAs
    convert_T_kernel<<<(DIN * UNITS) / 256, 256>>>(T);           // 512 CTAs

    dim3 gg(UNITS / 128, M_TOT / 128);                           // (4, 256)
    gemm_kernel<<<gg, 512, 2 * GS_STAGE>>>();

    dim3 gs(UNITS / 128, BATCH);                                 // (4, 64)
    scan_kernel<<<gs, 64, 65536>>>(B, bias, h0, out);
}